// round 6
// baseline (speedup 1.0000x reference)
#include <cuda_runtime.h>
#include <math.h>

// ---------------- problem dims ----------------
#define TT   1024
#define DD   1024
#define DFFN 1024
#define RR   64
#define GG   8
#define EE   32
#define NEXPN 256
#define KK   8
#define FF   (TT*KK)      // 8192 routed pairs
#define MAX_TILES 136     // sum_g ceil(cnt_g/64) <= 8192/64 + (G-1) padded to 136

// ---------------- GEMM tiling ----------------
#define BM 64
#define BN 64
#define BK 16

// ---------------- device scratch (no allocs allowed) ----------------
__device__ float g_logits[TT*NEXPN];
__device__ int   g_pair_e[FF];
__device__ float g_pair_w[FF];
__device__ int   g_sf[FF];          // sorted pos -> original pair f
__device__ int   g_se[FF];          // expert id at sorted pos
__device__ float g_sw[FF];          // routing weight at sorted pos
__device__ int   g_stok[FF];        // token id at sorted pos
__device__ int   g_off[GG+1];       // group offsets in sorted order
__device__ int   g_tile_g[MAX_TILES];
__device__ int   g_tile_row[MAX_TILES];
__device__ int   g_ntiles;
__device__ float g_pre_gate[GG*TT*RR];
__device__ float g_pre_up  [GG*TT*RR];
// +64 row padding: partial tiles over-read A harmlessly (writes are guarded)
__device__ float g_xg [(FF+64)*RR];
__device__ float g_xu [(FF+64)*RR];
__device__ float g_act[(FF+64)*DFFN];
__device__ float g_xd [FF*RR];
__device__ float g_x2 [(FF+64)*RR];
__device__ float g_outf[FF*DD];

// ---------------- tiled-GEMM helpers (fp32, 256 thr, 4x4/thread) ----------------
__device__ __forceinline__ void load_tiles(
    float Asm[BK][BM+4], float Bsm[BK][BN],
    const float* __restrict__ A, int lda,
    const float* __restrict__ B, int ldb,
    int k0, int tid)
{
    // A tile: 64 rows x 16 cols, one float4 per thread, stored transposed
    float4 av = *(const float4*)(A + (tid>>2)*lda + k0 + (tid&3)*4);
    int c = (tid&3)*4, r = tid>>2;
    Asm[c+0][r] = av.x; Asm[c+1][r] = av.y; Asm[c+2][r] = av.z; Asm[c+3][r] = av.w;
    // B tile: 16 rows x 64 cols, one float4 per thread
    float4 bv = *(const float4*)(B + (k0 + (tid>>4))*ldb + (tid&15)*4);
    *(float4*)(&Bsm[tid>>4][(tid&15)*4]) = bv;
}

__device__ __forceinline__ void mma_step(
    const float Asm[BK][BM+4], const float Bsm[BK][BN],
    float acc[4][4], int ty4, int tx4)
{
#pragma unroll
    for (int k = 0; k < BK; k++) {
        float a[4], b[4];
#pragma unroll
        for (int i = 0; i < 4; i++) a[i] = Asm[k][ty4+i];
#pragma unroll
        for (int j = 0; j < 4; j++) b[j] = Bsm[k][tx4+j];
#pragma unroll
        for (int i = 0; i < 4; i++)
#pragma unroll
            for (int j = 0; j < 4; j++)
                acc[i][j] += a[i] * b[j];
    }
}

// ---------------- K1: router logits = x @ Wg ----------------
__global__ __launch_bounds__(256) void k_logits(
    const float* __restrict__ x, const float* __restrict__ Wg)
{
    __shared__ float Asm[BK][BM+4];
    __shared__ float Bsm[BK][BN];
    int tid = threadIdx.x, tx4 = (tid&15)*4, ty4 = (tid>>4)*4;
    const float* A = x  + blockIdx.x*BM*DD;
    const float* B = Wg + blockIdx.y*BN;
    float acc[4][4] = {};
    for (int k0 = 0; k0 < DD; k0 += BK) {
        load_tiles(Asm, Bsm, A, DD, B, NEXPN, k0, tid);
        __syncthreads();
        mma_step(Asm, Bsm, acc, ty4, tx4);
        __syncthreads();
    }
    float* C = g_logits + (blockIdx.x*BM + ty4)*NEXPN + blockIdx.y*BN + tx4;
#pragma unroll
    for (int i = 0; i < 4; i++)
        *(float4*)(C + i*NEXPN) = make_float4(acc[i][0], acc[i][1], acc[i][2], acc[i][3]);
}

// ---------------- K2: per-token top-8 + softmax (one warp per token) ----------------
__global__ void k_topk()
{
    int t    = (blockIdx.x*blockDim.x + threadIdx.x) >> 5;
    int lane = threadIdx.x & 31;
    if (t >= TT) return;
    const float* lp = g_logits + t*NEXPN;
    float v[8];
#pragma unroll
    for (int i = 0; i < 8; i++) v[i] = lp[lane + i*32];
    float tv[KK]; int ti_[KK];
    for (int k = 0; k < KK; k++) {
        float bv = -INFINITY; int bi = NEXPN;
#pragma unroll
        for (int i = 0; i < 8; i++) {
            int idx = lane + i*32;
            if (v[i] > bv || (v[i] == bv && idx < bi)) { bv = v[i]; bi = idx; }
        }
#pragma unroll
        for (int s = 16; s; s >>= 1) {
            float ov = __shfl_xor_sync(0xffffffffu, bv, s);
            int   oi = __shfl_xor_sync(0xffffffffu, bi, s);
            if (ov > bv || (ov == bv && oi < bi)) { bv = ov; bi = oi; }
        }
        tv[k] = bv; ti_[k] = bi;
#pragma unroll
        for (int i = 0; i < 8; i++)
            if (bi == lane + i*32) v[i] = -INFINITY;  // remove winner
    }
    if (lane == 0) {
        float mx = tv[0], s = 0.f, ev[KK];
#pragma unroll
        for (int k = 0; k < KK; k++) { ev[k] = expf(tv[k] - mx); s += ev[k]; }
        float inv = 1.f / s;
#pragma unroll
        for (int k = 0; k < KK; k++) {
            g_pair_e[t*KK + k] = ti_[k];
            g_pair_w[t*KK + k] = ev[k] * inv;
        }
    }
}

// ---------------- K3: counting sort by group + tile list (single block) ----------------
__global__ void k_sort()
{
    __shared__ int cnt[GG], cur[GG];
    int tid = threadIdx.x;
    if (tid < GG) cnt[tid] = 0;
    __syncthreads();
    for (int f = tid; f < FF; f += blockDim.x)
        atomicAdd(&cnt[g_pair_e[f] >> 5], 1);
    __syncthreads();
    if (tid == 0) {
        int o = 0, nt = 0;
        for (int g = 0; g < GG; g++) {
            g_off[g] = o; cur[g] = o;
            for (int r = 0; r < cnt[g]; r += BM) {
                g_tile_g[nt] = g; g_tile_row[nt] = o + r; nt++;
            }
            o += cnt[g];
        }
        g_off[GG] = o;
        g_ntiles = nt;
    }
    __syncthreads();
    for (int f = tid; f < FF; f += blockDim.x) {
        int e = g_pair_e[f];
        int p = atomicAdd(&cur[e >> 5], 1);
        g_sf[p] = f; g_se[p] = e; g_sw[p] = g_pair_w[f]; g_stok[p] = f >> 3;
    }
}

// ---------------- K4: pre = x @ uin[g] for all groups (gate & up via z) ----------------
__global__ __launch_bounds__(256) void k_pre(
    const float* __restrict__ x,
    const float* __restrict__ uin_gate, const float* __restrict__ uin_up)
{
    __shared__ float Asm[BK][BM+4];
    __shared__ float Bsm[BK][BN];
    int tid = threadIdx.x, tx4 = (tid&15)*4, ty4 = (tid>>4)*4;
    int g = blockIdx.y;
    const float* A = x + blockIdx.x*BM*DD;
    const float* B = (blockIdx.z ? uin_up : uin_gate) + g*DD*RR;
    float* Cb = (blockIdx.z ? g_pre_up : g_pre_gate) + g*TT*RR + blockIdx.x*BM*RR;
    float acc[4][4] = {};
    for (int k0 = 0; k0 < DD; k0 += BK) {
        load_tiles(Asm, Bsm, A, DD, B, RR, k0, tid);
        __syncthreads();
        mma_step(Asm, Bsm, acc, ty4, tx4);
        __syncthreads();
    }
#pragma unroll
    for (int i = 0; i < 4; i++)
        *(float4*)(Cb + (ty4+i)*RR + tx4) = make_float4(acc[i][0], acc[i][1], acc[i][2], acc[i][3]);
}

// ---------------- K5: Tucker core apply (gate & up), one pair per 64-thr block ----------------
__global__ void k_core_gu(
    const float* __restrict__ core_gate, const float* __restrict__ core_up)
{
    int p = blockIdx.x;
    int e = g_se[p], g = e >> 5, t = g_stok[p];
    const float* core; const float* xin; float* xo;
    if (blockIdx.y == 0) {
        core = core_gate + e*RR*RR; xin = g_pre_gate + (g*TT + t)*RR; xo = g_xg + p*RR;
    } else {
        core = core_up   + e*RR*RR; xin = g_pre_up   + (g*TT + t)*RR; xo = g_xu + p*RR;
    }
    __shared__ float xs[RR];
    int j = threadIdx.x;
    xs[j] = xin[j];
    __syncthreads();
    float acc = 0.f;
#pragma unroll 8
    for (int r = 0; r < RR; r++) acc += xs[r] * core[r*RR + j];
    xo[j] = acc;
}

// ---------------- K6: fused SwiGLU group-GEMM: act = silu(Hg@Ug) * (Hu@Uu) ----------------
__global__ __launch_bounds__(256) void k_swiglu(
    const float* __restrict__ uout_gate, const float* __restrict__ uout_up)
{
    int ti = blockIdx.x;
    if (ti >= g_ntiles) return;
    int g = g_tile_g[ti], row0 = g_tile_row[ti], rend = g_off[g+1];
    int n0 = blockIdx.y*BN;
    __shared__ float Ag[BK][BM+4], Au[BK][BM+4];
    __shared__ float Bg[BK][BN],   Bu[BK][BN];
    int tid = threadIdx.x, tx4 = (tid&15)*4, ty4 = (tid>>4)*4;
    const float* Agp = g_xg + row0*RR;
    const float* Aup = g_xu + row0*RR;
    const float* Bgp = uout_gate + g*RR*DFFN + n0;
    const float* Bup = uout_up   + g*RR*DFFN + n0;
    float accg[4][4] = {}, accu[4][4] = {};
    for (int k0 = 0; k0 < RR; k0 += BK) {
        load_tiles(Ag, Bg, Agp, RR, Bgp, DFFN, k0, tid);
        load_tiles(Au, Bu, Aup, RR, Bup, DFFN, k0, tid);
        __syncthreads();
        mma_step(Ag, Bg, accg, ty4, tx4);
        mma_step(Au, Bu, accu, ty4, tx4);
        __syncthreads();
    }
#pragma unroll
    for (int i = 0; i < 4; i++) {
        int p = row0 + ty4 + i;
        if (p < rend) {
            float4 v;
#pragma unroll
            for (int j = 0; j < 4; j++) {
                float gv = accg[i][j];
                ((float*)&v)[j] = (gv / (1.f + expf(-gv))) * accu[i][j];
            }
            *(float4*)(g_act + p*DFFN + n0 + tx4) = v;
        }
    }
}

// ---------------- K7: xd = act @ uin_down[g]  (K=1024, N=64) ----------------
__global__ __launch_bounds__(256) void k_down_in(const float* __restrict__ uin_down)
{
    int ti = blockIdx.x;
    if (ti >= g_ntiles) return;
    int g = g_tile_g[ti], row0 = g_tile_row[ti], rend = g_off[g+1];
    __shared__ float Asm[BK][BM+4], Bsm[BK][BN];
    int tid = threadIdx.x, tx4 = (tid&15)*4, ty4 = (tid>>4)*4;
    const float* A = g_act + row0*DFFN;
    const float* B = uin_down + g*DFFN*RR;
    float acc[4][4] = {};
    for (int k0 = 0; k0 < DFFN; k0 += BK) {
        load_tiles(Asm, Bsm, A, DFFN, B, RR, k0, tid);
        __syncthreads();
        mma_step(Asm, Bsm, acc, ty4, tx4);
        __syncthreads();
    }
#pragma unroll
    for (int i = 0; i < 4; i++) {
        int p = row0 + ty4 + i;
        if (p < rend)
            *(float4*)(g_xd + p*RR + tx4) = make_float4(acc[i][0], acc[i][1], acc[i][2], acc[i][3]);
    }
}

// ---------------- K8: Tucker core apply (down) ----------------
__global__ void k_core_down(const float* __restrict__ core_down)
{
    int p = blockIdx.x;
    int e = g_se[p];
    const float* core = core_down + e*RR*RR;
    __shared__ float xs[RR];
    int j = threadIdx.x;
    xs[j] = g_xd[p*RR + j];
    __syncthreads();
    float acc = 0.f;
#pragma unroll 8
    for (int r = 0; r < RR; r++) acc += xs[r] * core[r*RR + j];
    g_x2[p*RR + j] = acc;
}

// ---------------- K9: out_f[f] = w[f] * (x2 @ uout_down[g]) (written in ORIGINAL pair order) ----------------
__global__ __launch_bounds__(256) void k_out(const float* __restrict__ uout_down)
{
    int ti = blockIdx.x;
    if (ti >= g_ntiles) return;
    int g = g_tile_g[ti], row0 = g_tile_row[ti], rend = g_off[g+1];
    int n0 = blockIdx.y*BN;
    __shared__ float Asm[BK][BM+4], Bsm[BK][BN];
    int tid = threadIdx.x, tx4 = (tid&15)*4, ty4 = (tid>>4)*4;
    const float* A = g_x2 + row0*RR;
    const float* B = uout_down + g*RR*DD + n0;
    float acc[4][4] = {};
    for (int k0 = 0; k0 < RR; k0 += BK) {
        load_tiles(Asm, Bsm, A, RR, B, DD, k0, tid);
        __syncthreads();
        mma_step(Asm, Bsm, acc, ty4, tx4);
        __syncthreads();
    }
#pragma unroll
    for (int i = 0; i < 4; i++) {
        int p = row0 + ty4 + i;
        if (p < rend) {
            int f = g_sf[p];
            float w = g_sw[p];
            *(float4*)(g_outf + f*DD + n0 + tx4) =
                make_float4(acc[i][0]*w, acc[i][1]*w, acc[i][2]*w, acc[i][3]*w);
        }
    }
}

// ---------------- K10: deterministic segment-sum (K=8 contiguous rows per token) ----------------
__global__ void k_reduce(float* __restrict__ out)
{
    int d = blockIdx.x*blockDim.x + threadIdx.x;
    int t = blockIdx.y;
    float s = 0.f;
#pragma unroll
    for (int k = 0; k < KK; k++) s += g_outf[(t*KK + k)*DD + d];
    out[t*DD + d] = s;
}

// ---------------- launch ----------------
extern "C" void kernel_launch(void* const* d_in, const int* in_sizes, int n_in,
                              void* d_out, int out_size)
{
    const float* x         = (const float*)d_in[0];
    const float* Wg        = (const float*)d_in[1];
    const float* uin_gate  = (const float*)d_in[2];
    const float* core_gate = (const float*)d_in[3];
    const float* uout_gate = (const float*)d_in[4];
    const float* uin_up    = (const float*)d_in[5];
    const float* core_up   = (const float*)d_in[6];
    const float* uout_up   = (const float*)d_in[7];
    const float* uin_down  = (const float*)d_in[8];
    const float* core_down = (const float*)d_in[9];
    const float* uout_down = (const float*)d_in[10];
    float* out = (float*)d_out;

    k_logits   <<<dim3(TT/BM, NEXPN/BN), 256>>>(x, Wg);
    k_topk     <<<(TT*32 + 255)/256, 256>>>();
    k_sort     <<<1, 1024>>>();
    k_pre      <<<dim3(TT/BM, GG, 2), 256>>>(x, uin_gate, uin_up);
    k_core_gu  <<<dim3(FF, 2), RR>>>(core_gate, core_up);
    k_swiglu   <<<dim3(MAX_TILES, DFFN/BN), 256>>>(uout_gate, uout_up);
    k_down_in  <<<MAX_TILES, 256>>>(uin_down);
    k_core_down<<<FF, RR>>>(core_down);
    k_out      <<<dim3(MAX_TILES, DD/BN), 256>>>(uout_down);
    k_reduce   <<<dim3(DD/256, TT), 256>>>(out);
}

// round 9
// speedup vs baseline: 1.0056x; 1.0056x over previous
#include <cuda_runtime.h>
#include <math.h>

// ---------------- problem dims ----------------
#define TT   1024
#define DD   1024
#define DFFN 1024
#define RR   64
#define GG   8
#define EE   32
#define NEXPN 256
#define KK   8
#define FF   (TT*KK)      // 8192 routed pairs
#define MAX_TILES 136     // sum_g ceil(cnt_g/64) <= 8192/64 + (G-1) padded to 136

// ---------------- GEMM tiling ----------------
#define BM 64
#define BN 64
#define BK 16

// ---------------- device scratch (no allocs allowed) ----------------
__device__ float g_logits[TT*NEXPN];
__device__ int   g_pair_e[FF];
__device__ float g_pair_w[FF];
__device__ int   g_sf[FF];          // sorted pos -> original pair f
__device__ int   g_se[FF];          // expert id at sorted pos
__device__ float g_sw[FF];          // routing weight at sorted pos
__device__ int   g_stok[FF];        // token id at sorted pos
__device__ int   g_off[GG+1];       // group offsets in sorted order
__device__ int   g_tile_g[MAX_TILES];
__device__ int   g_tile_row[MAX_TILES];
__device__ int   g_ntiles;
__device__ float g_pre_gate[GG*TT*RR];
__device__ float g_pre_up  [GG*TT*RR];
// +64 row padding: partial tiles over-read A harmlessly (writes are guarded)
__device__ float g_xg [(FF+64)*RR];
__device__ float g_xu [(FF+64)*RR];
__device__ float g_act[(FF+64)*DFFN];
__device__ float g_xd [FF*RR];
__device__ float g_x2 [(FF+64)*RR];
__device__ float g_outf[FF*DD];

// ---------------- tiled-GEMM helpers (fp32, 256 thr, 4x4/thread) ----------------
__device__ __forceinline__ void load_tiles(
    float Asm[BK][BM+4], float Bsm[BK][BN],
    const float* __restrict__ A, int lda,
    const float* __restrict__ B, int ldb,
    int k0, int tid)
{
    // A tile: 64 rows x 16 cols, one float4 per thread, stored transposed
    float4 av = *(const float4*)(A + (tid>>2)*lda + k0 + (tid&3)*4);
    int c = (tid&3)*4, r = tid>>2;
    Asm[c+0][r] = av.x; Asm[c+1][r] = av.y; Asm[c+2][r] = av.z; Asm[c+3][r] = av.w;
    // B tile: 16 rows x 64 cols, one float4 per thread
    float4 bv = *(const float4*)(B + (k0 + (tid>>4))*ldb + (tid&15)*4);
    *(float4*)(&Bsm[tid>>4][(tid&15)*4]) = bv;
}

__device__ __forceinline__ void mma_step(
    const float Asm[BK][BM+4], const float Bsm[BK][BN],
    float acc[4][4], int ty4, int tx4)
{
#pragma unroll
    for (int k = 0; k < BK; k++) {
        float a[4], b[4];
#pragma unroll
        for (int i = 0; i < 4; i++) a[i] = Asm[k][ty4+i];
#pragma unroll
        for (int j = 0; j < 4; j++) b[j] = Bsm[k][tx4+j];
#pragma unroll
        for (int i = 0; i < 4; i++)
#pragma unroll
            for (int j = 0; j < 4; j++)
                acc[i][j] += a[i] * b[j];
    }
}

// ---------------- K1: router logits = x @ Wg ----------------
__global__ __launch_bounds__(256) void k_logits(
    const float* __restrict__ x, const float* __restrict__ Wg)
{
    __shared__ float Asm[BK][BM+4];
    __shared__ float Bsm[BK][BN];
    int tid = threadIdx.x, tx4 = (tid&15)*4, ty4 = (tid>>4)*4;
    const float* A = x  + blockIdx.x*BM*DD;
    const float* B = Wg + blockIdx.y*BN;
    float acc[4][4] = {};
    for (int k0 = 0; k0 < DD; k0 += BK) {
        load_tiles(Asm, Bsm, A, DD, B, NEXPN, k0, tid);
        __syncthreads();
        mma_step(Asm, Bsm, acc, ty4, tx4);
        __syncthreads();
    }
    float* C = g_logits + (blockIdx.x*BM + ty4)*NEXPN + blockIdx.y*BN + tx4;
#pragma unroll
    for (int i = 0; i < 4; i++)
        *(float4*)(C + i*NEXPN) = make_float4(acc[i][0], acc[i][1], acc[i][2], acc[i][3]);
}

// ---------------- K2: per-token top-8 + softmax (one warp per token) ----------------
__global__ void k_topk()
{
    int t    = (blockIdx.x*blockDim.x + threadIdx.x) >> 5;
    int lane = threadIdx.x & 31;
    if (t >= TT) return;
    const float* lp = g_logits + t*NEXPN;
    float v[8];
#pragma unroll
    for (int i = 0; i < 8; i++) v[i] = lp[lane + i*32];
    float tv[KK]; int ti_[KK];
    for (int k = 0; k < KK; k++) {
        float bv = -INFINITY; int bi = NEXPN;
#pragma unroll
        for (int i = 0; i < 8; i++) {
            int idx = lane + i*32;
            if (v[i] > bv || (v[i] == bv && idx < bi)) { bv = v[i]; bi = idx; }
        }
#pragma unroll
        for (int s = 16; s; s >>= 1) {
            float ov = __shfl_xor_sync(0xffffffffu, bv, s);
            int   oi = __shfl_xor_sync(0xffffffffu, bi, s);
            if (ov > bv || (ov == bv && oi < bi)) { bv = ov; bi = oi; }
        }
        tv[k] = bv; ti_[k] = bi;
#pragma unroll
        for (int i = 0; i < 8; i++)
            if (bi == lane + i*32) v[i] = -INFINITY;  // remove winner
    }
    if (lane == 0) {
        float mx = tv[0], s = 0.f, ev[KK];
#pragma unroll
        for (int k = 0; k < KK; k++) { ev[k] = expf(tv[k] - mx); s += ev[k]; }
        float inv = 1.f / s;
#pragma unroll
        for (int k = 0; k < KK; k++) {
            g_pair_e[t*KK + k] = ti_[k];
            g_pair_w[t*KK + k] = ev[k] * inv;
        }
    }
}

// ---------------- K3: counting sort by group + tile list (single block) ----------------
__global__ void k_sort()
{
    __shared__ int cnt[GG], cur[GG];
    int tid = threadIdx.x;
    if (tid < GG) cnt[tid] = 0;
    __syncthreads();
    for (int f = tid; f < FF; f += blockDim.x)
        atomicAdd(&cnt[g_pair_e[f] >> 5], 1);
    __syncthreads();
    if (tid == 0) {
        int o = 0, nt = 0;
        for (int g = 0; g < GG; g++) {
            g_off[g] = o; cur[g] = o;
            for (int r = 0; r < cnt[g]; r += BM) {
                g_tile_g[nt] = g; g_tile_row[nt] = o + r; nt++;
            }
            o += cnt[g];
        }
        g_off[GG] = o;
        g_ntiles = nt;
    }
    __syncthreads();
    for (int f = tid; f < FF; f += blockDim.x) {
        int e = g_pair_e[f];
        int p = atomicAdd(&cur[e >> 5], 1);
        g_sf[p] = f; g_se[p] = e; g_sw[p] = g_pair_w[f]; g_stok[p] = f >> 3;
    }
}

// ---------------- K4: pre = x @ uin[g] for all groups (gate & up via z) ----------------
__global__ __launch_bounds__(256) void k_pre(
    const float* __restrict__ x,
    const float* __restrict__ uin_gate, const float* __restrict__ uin_up)
{
    __shared__ float Asm[BK][BM+4];
    __shared__ float Bsm[BK][BN];
    int tid = threadIdx.x, tx4 = (tid&15)*4, ty4 = (tid>>4)*4;
    int g = blockIdx.y;
    const float* A = x + blockIdx.x*BM*DD;
    const float* B = (blockIdx.z ? uin_up : uin_gate) + g*DD*RR;
    float* Cb = (blockIdx.z ? g_pre_up : g_pre_gate) + g*TT*RR + blockIdx.x*BM*RR;
    float acc[4][4] = {};
    for (int k0 = 0; k0 < DD; k0 += BK) {
        load_tiles(Asm, Bsm, A, DD, B, RR, k0, tid);
        __syncthreads();
        mma_step(Asm, Bsm, acc, ty4, tx4);
        __syncthreads();
    }
#pragma unroll
    for (int i = 0; i < 4; i++)
        *(float4*)(Cb + (ty4+i)*RR + tx4) = make_float4(acc[i][0], acc[i][1], acc[i][2], acc[i][3]);
}

// ---------------- K5: Tucker core apply (gate & up), one pair per 64-thr block ----------------
__global__ void k_core_gu(
    const float* __restrict__ core_gate, const float* __restrict__ core_up)
{
    int p = blockIdx.x;
    int e = g_se[p], g = e >> 5, t = g_stok[p];
    const float* core; const float* xin; float* xo;
    if (blockIdx.y == 0) {
        core = core_gate + e*RR*RR; xin = g_pre_gate + (g*TT + t)*RR; xo = g_xg + p*RR;
    } else {
        core = core_up   + e*RR*RR; xin = g_pre_up   + (g*TT + t)*RR; xo = g_xu + p*RR;
    }
    __shared__ float xs[RR];
    int j = threadIdx.x;
    xs[j] = xin[j];
    __syncthreads();
    float acc = 0.f;
#pragma unroll 8
    for (int r = 0; r < RR; r++) acc += xs[r] * core[r*RR + j];
    xo[j] = acc;
}

// ---------------- K6: fused SwiGLU group-GEMM: act = silu(Hg@Ug) * (Hu@Uu) ----------------
__global__ __launch_bounds__(256) void k_swiglu(
    const float* __restrict__ uout_gate, const float* __restrict__ uout_up)
{
    int ti = blockIdx.x;
    if (ti >= g_ntiles) return;
    int g = g_tile_g[ti], row0 = g_tile_row[ti], rend = g_off[g+1];
    int n0 = blockIdx.y*BN;
    __shared__ float Ag[BK][BM+4], Au[BK][BM+4];
    __shared__ float Bg[BK][BN],   Bu[BK][BN];
    int tid = threadIdx.x, tx4 = (tid&15)*4, ty4 = (tid>>4)*4;
    const float* Agp = g_xg + row0*RR;
    const float* Aup = g_xu + row0*RR;
    const float* Bgp = uout_gate + g*RR*DFFN + n0;
    const float* Bup = uout_up   + g*RR*DFFN + n0;
    float accg[4][4] = {}, accu[4][4] = {};
    for (int k0 = 0; k0 < RR; k0 += BK) {
        load_tiles(Ag, Bg, Agp, RR, Bgp, DFFN, k0, tid);
        load_tiles(Au, Bu, Aup, RR, Bup, DFFN, k0, tid);
        __syncthreads();
        mma_step(Ag, Bg, accg, ty4, tx4);
        mma_step(Au, Bu, accu, ty4, tx4);
        __syncthreads();
    }
#pragma unroll
    for (int i = 0; i < 4; i++) {
        int p = row0 + ty4 + i;
        if (p < rend) {
            float4 v;
#pragma unroll
            for (int j = 0; j < 4; j++) {
                float gv = accg[i][j];
                ((float*)&v)[j] = (gv / (1.f + expf(-gv))) * accu[i][j];
            }
            *(float4*)(g_act + p*DFFN + n0 + tx4) = v;
        }
    }
}

// ---------------- K7: xd = act @ uin_down[g]  (K=1024, N=64) ----------------
__global__ __launch_bounds__(256) void k_down_in(const float* __restrict__ uin_down)
{
    int ti = blockIdx.x;
    if (ti >= g_ntiles) return;
    int g = g_tile_g[ti], row0 = g_tile_row[ti], rend = g_off[g+1];
    __shared__ float Asm[BK][BM+4], Bsm[BK][BN];
    int tid = threadIdx.x, tx4 = (tid&15)*4, ty4 = (tid>>4)*4;
    const float* A = g_act + row0*DFFN;
    const float* B = uin_down + g*DFFN*RR;
    float acc[4][4] = {};
    for (int k0 = 0; k0 < DFFN; k0 += BK) {
        load_tiles(Asm, Bsm, A, DFFN, B, RR, k0, tid);
        __syncthreads();
        mma_step(Asm, Bsm, acc, ty4, tx4);
        __syncthreads();
    }
#pragma unroll
    for (int i = 0; i < 4; i++) {
        int p = row0 + ty4 + i;
        if (p < rend)
            *(float4*)(g_xd + p*RR + tx4) = make_float4(acc[i][0], acc[i][1], acc[i][2], acc[i][3]);
    }
}

// ---------------- K8: Tucker core apply (down) ----------------
__global__ void k_core_down(const float* __restrict__ core_down)
{
    int p = blockIdx.x;
    int e = g_se[p];
    const float* core = core_down + e*RR*RR;
    __shared__ float xs[RR];
    int j = threadIdx.x;
    xs[j] = g_xd[p*RR + j];
    __syncthreads();
    float acc = 0.f;
#pragma unroll 8
    for (int r = 0; r < RR; r++) acc += xs[r] * core[r*RR + j];
    g_x2[p*RR + j] = acc;
}

// ---------------- K9: out_f[f] = w[f] * (x2 @ uout_down[g]) (written in ORIGINAL pair order) ----------------
__global__ __launch_bounds__(256) void k_out(const float* __restrict__ uout_down)
{
    int ti = blockIdx.x;
    if (ti >= g_ntiles) return;
    int g = g_tile_g[ti], row0 = g_tile_row[ti], rend = g_off[g+1];
    int n0 = blockIdx.y*BN;
    __shared__ float Asm[BK][BM+4], Bsm[BK][BN];
    int tid = threadIdx.x, tx4 = (tid&15)*4, ty4 = (tid>>4)*4;
    const float* A = g_x2 + row0*RR;
    const float* B = uout_down + g*RR*DD + n0;
    float acc[4][4] = {};
    for (int k0 = 0; k0 < RR; k0 += BK) {
        load_tiles(Asm, Bsm, A, RR, B, DD, k0, tid);
        __syncthreads();
        mma_step(Asm, Bsm, acc, ty4, tx4);
        __syncthreads();
    }
#pragma unroll
    for (int i = 0; i < 4; i++) {
        int p = row0 + ty4 + i;
        if (p < rend) {
            int f = g_sf[p];
            float w = g_sw[p];
            *(float4*)(g_outf + f*DD + n0 + tx4) =
                make_float4(acc[i][0]*w, acc[i][1]*w, acc[i][2]*w, acc[i][3]*w);
        }
    }
}

// ---------------- K10: deterministic segment-sum (K=8 contiguous rows per token) ----------------
__global__ void k_reduce(float* __restrict__ out)
{
    int d = blockIdx.x*blockDim.x + threadIdx.x;
    int t = blockIdx.y;
    float s = 0.f;
#pragma unroll
    for (int k = 0; k < KK; k++) s += g_outf[(t*KK + k)*DD + d];
    out[t*DD + d] = s;
}

// ---------------- launch ----------------
extern "C" void kernel_launch(void* const* d_in, const int* in_sizes, int n_in,
                              void* d_out, int out_size)
{
    const float* x         = (const float*)d_in[0];
    const float* Wg        = (const float*)d_in[1];
    const float* uin_gate  = (const float*)d_in[2];
    const float* core_gate = (const float*)d_in[3];
    const float* uout_gate = (const float*)d_in[4];
    const float* uin_up    = (const float*)d_in[5];
    const float* core_up   = (const float*)d_in[6];
    const float* uout_up   = (const float*)d_in[7];
    const float* uin_down  = (const float*)d_in[8];
    const float* core_down = (const float*)d_in[9];
    const float* uout_down = (const float*)d_in[10];
    float* out = (float*)d_out;

    k_logits   <<<dim3(TT/BM, NEXPN/BN), 256>>>(x, Wg);
    k_topk     <<<(TT*32 + 255)/256, 256>>>();
    k_sort     <<<1, 1024>>>();
    k_pre      <<<dim3(TT/BM, GG, 2), 256>>>(x, uin_gate, uin_up);
    k_core_gu  <<<dim3(FF, 2), RR>>>(core_gate, core_up);
    k_swiglu   <<<dim3(MAX_TILES, DFFN/BN), 256>>>(uout_gate, uout_up);
    k_down_in  <<<MAX_TILES, 256>>>(uin_down);
    k_core_down<<<FF, RR>>>(core_down);
    k_out      <<<dim3(MAX_TILES, DD/BN), 256>>>(uout_down);
    k_reduce   <<<dim3(DD/256, TT), 256>>>(out);
}

// round 10
// speedup vs baseline: 1.0099x; 1.0043x over previous
#include <cuda_runtime.h>
#include <math.h>

// ---------------- problem dims ----------------
#define TT   1024
#define DD   1024
#define DFFN 1024
#define RR   64
#define GG   8
#define EE   32
#define NEXPN 256
#define KK   8
#define FF   (TT*KK)      // 8192 routed pairs
#define MAX_TILES 136     // sum_g ceil(cnt_g/64) <= 8192/64 + (G-1) padded to 136

// ---------------- GEMM tiling ----------------
#define BM 64
#define BN 64
#define BK 16

// ---------------- device scratch (no allocs allowed) ----------------
__device__ float g_logits[TT*NEXPN];
__device__ int   g_pair_e[FF];
__device__ float g_pair_w[FF];
__device__ int   g_sf[FF];          // sorted pos -> original pair f
__device__ int   g_se[FF];          // expert id at sorted pos
__device__ float g_sw[FF];          // routing weight at sorted pos
__device__ int   g_stok[FF];        // token id at sorted pos
__device__ int   g_off[GG+1];       // group offsets in sorted order
__device__ int   g_tile_g[MAX_TILES];
__device__ int   g_tile_row[MAX_TILES];
__device__ int   g_ntiles;
__device__ float g_pre_gate[GG*TT*RR];
__device__ float g_pre_up  [GG*TT*RR];
// +64 row padding: partial tiles over-read A harmlessly (writes are guarded)
__device__ float g_xg [(FF+64)*RR];
__device__ float g_xu [(FF+64)*RR];
__device__ float g_act[(FF+64)*DFFN];
__device__ float g_xd [FF*RR];
__device__ float g_x2 [(FF+64)*RR];
__device__ float g_outf[FF*DD];

// ---------------- tiled-GEMM helpers (fp32, 256 thr, 4x4/thread) ----------------
__device__ __forceinline__ void load_tiles(
    float Asm[BK][BM+4], float Bsm[BK][BN],
    const float* __restrict__ A, int lda,
    const float* __restrict__ B, int ldb,
    int k0, int tid)
{
    // A tile: 64 rows x 16 cols, one float4 per thread, stored transposed
    float4 av = *(const float4*)(A + (tid>>2)*lda + k0 + (tid&3)*4);
    int c = (tid&3)*4, r = tid>>2;
    Asm[c+0][r] = av.x; Asm[c+1][r] = av.y; Asm[c+2][r] = av.z; Asm[c+3][r] = av.w;
    // B tile: 16 rows x 64 cols, one float4 per thread
    float4 bv = *(const float4*)(B + (k0 + (tid>>4))*ldb + (tid&15)*4);
    *(float4*)(&Bsm[tid>>4][(tid&15)*4]) = bv;
}

__device__ __forceinline__ void mma_step(
    const float Asm[BK][BM+4], const float Bsm[BK][BN],
    float acc[4][4], int ty4, int tx4)
{
#pragma unroll
    for (int k = 0; k < BK; k++) {
        float a[4], b[4];
#pragma unroll
        for (int i = 0; i < 4; i++) a[i] = Asm[k][ty4+i];
#pragma unroll
        for (int j = 0; j < 4; j++) b[j] = Bsm[k][tx4+j];
#pragma unroll
        for (int i = 0; i < 4; i++)
#pragma unroll
            for (int j = 0; j < 4; j++)
                acc[i][j] += a[i] * b[j];
    }
}

// ---------------- K1: router logits = x @ Wg ----------------
__global__ __launch_bounds__(256) void k_logits(
    const float* __restrict__ x, const float* __restrict__ Wg)
{
    __shared__ float Asm[BK][BM+4];
    __shared__ float Bsm[BK][BN];
    int tid = threadIdx.x, tx4 = (tid&15)*4, ty4 = (tid>>4)*4;
    const float* A = x  + blockIdx.x*BM*DD;
    const float* B = Wg + blockIdx.y*BN;
    float acc[4][4] = {};
    for (int k0 = 0; k0 < DD; k0 += BK) {
        load_tiles(Asm, Bsm, A, DD, B, NEXPN, k0, tid);
        __syncthreads();
        mma_step(Asm, Bsm, acc, ty4, tx4);
        __syncthreads();
    }
    float* C = g_logits + (blockIdx.x*BM + ty4)*NEXPN + blockIdx.y*BN + tx4;
#pragma unroll
    for (int i = 0; i < 4; i++)
        *(float4*)(C + i*NEXPN) = make_float4(acc[i][0], acc[i][1], acc[i][2], acc[i][3]);
}

// ---------------- K2: per-token top-8 + softmax (one warp per token) ----------------
__global__ void k_topk()
{
    int t    = (blockIdx.x*blockDim.x + threadIdx.x) >> 5;
    int lane = threadIdx.x & 31;
    if (t >= TT) return;
    const float* lp = g_logits + t*NEXPN;
    float v[8];
#pragma unroll
    for (int i = 0; i < 8; i++) v[i] = lp[lane + i*32];
    float tv[KK]; int ti_[KK];
    for (int k = 0; k < KK; k++) {
        float bv = -INFINITY; int bi = NEXPN;
#pragma unroll
        for (int i = 0; i < 8; i++) {
            int idx = lane + i*32;
            if (v[i] > bv || (v[i] == bv && idx < bi)) { bv = v[i]; bi = idx; }
        }
#pragma unroll
        for (int s = 16; s; s >>= 1) {
            float ov = __shfl_xor_sync(0xffffffffu, bv, s);
            int   oi = __shfl_xor_sync(0xffffffffu, bi, s);
            if (ov > bv || (ov == bv && oi < bi)) { bv = ov; bi = oi; }
        }
        tv[k] = bv; ti_[k] = bi;
#pragma unroll
        for (int i = 0; i < 8; i++)
            if (bi == lane + i*32) v[i] = -INFINITY;  // remove winner
    }
    if (lane == 0) {
        float mx = tv[0], s = 0.f, ev[KK];
#pragma unroll
        for (int k = 0; k < KK; k++) { ev[k] = expf(tv[k] - mx); s += ev[k]; }
        float inv = 1.f / s;
#pragma unroll
        for (int k = 0; k < KK; k++) {
            g_pair_e[t*KK + k] = ti_[k];
            g_pair_w[t*KK + k] = ev[k] * inv;
        }
    }
}

// ---------------- K3: counting sort by group + tile list (single block) ----------------
__global__ void k_sort()
{
    __shared__ int cnt[GG], cur[GG];
    int tid = threadIdx.x;
    if (tid < GG) cnt[tid] = 0;
    __syncthreads();
    for (int f = tid; f < FF; f += blockDim.x)
        atomicAdd(&cnt[g_pair_e[f] >> 5], 1);
    __syncthreads();
    if (tid == 0) {
        int o = 0, nt = 0;
        for (int g = 0; g < GG; g++) {
            g_off[g] = o; cur[g] = o;
            for (int r = 0; r < cnt[g]; r += BM) {
                g_tile_g[nt] = g; g_tile_row[nt] = o + r; nt++;
            }
            o += cnt[g];
        }
        g_off[GG] = o;
        g_ntiles = nt;
    }
    __syncthreads();
    for (int f = tid; f < FF; f += blockDim.x) {
        int e = g_pair_e[f];
        int p = atomicAdd(&cur[e >> 5], 1);
        g_sf[p] = f; g_se[p] = e; g_sw[p] = g_pair_w[f]; g_stok[p] = f >> 3;
    }
}

// ---------------- K4: pre = x @ uin[g] for all groups (gate & up via z) ----------------
__global__ __launch_bounds__(256) void k_pre(
    const float* __restrict__ x,
    const float* __restrict__ uin_gate, const float* __restrict__ uin_up)
{
    __shared__ float Asm[BK][BM+4];
    __shared__ float Bsm[BK][BN];
    int tid = threadIdx.x, tx4 = (tid&15)*4, ty4 = (tid>>4)*4;
    int g = blockIdx.y;
    const float* A = x + blockIdx.x*BM*DD;
    const float* B = (blockIdx.z ? uin_up : uin_gate) + g*DD*RR;
    float* Cb = (blockIdx.z ? g_pre_up : g_pre_gate) + g*TT*RR + blockIdx.x*BM*RR;
    float acc[4][4] = {};
    for (int k0 = 0; k0 < DD; k0 += BK) {
        load_tiles(Asm, Bsm, A, DD, B, RR, k0, tid);
        __syncthreads();
        mma_step(Asm, Bsm, acc, ty4, tx4);
        __syncthreads();
    }
#pragma unroll
    for (int i = 0; i < 4; i++)
        *(float4*)(Cb + (ty4+i)*RR + tx4) = make_float4(acc[i][0], acc[i][1], acc[i][2], acc[i][3]);
}

// ---------------- K5: Tucker core apply (gate & up), one pair per 64-thr block ----------------
__global__ void k_core_gu(
    const float* __restrict__ core_gate, const float* __restrict__ core_up)
{
    int p = blockIdx.x;
    int e = g_se[p], g = e >> 5, t = g_stok[p];
    const float* core; const float* xin; float* xo;
    if (blockIdx.y == 0) {
        core = core_gate + e*RR*RR; xin = g_pre_gate + (g*TT + t)*RR; xo = g_xg + p*RR;
    } else {
        core = core_up   + e*RR*RR; xin = g_pre_up   + (g*TT + t)*RR; xo = g_xu + p*RR;
    }
    __shared__ float xs[RR];
    int j = threadIdx.x;
    xs[j] = xin[j];
    __syncthreads();
    float acc = 0.f;
#pragma unroll 8
    for (int r = 0; r < RR; r++) acc += xs[r] * core[r*RR + j];
    xo[j] = acc;
}

// ---------------- K6: fused SwiGLU group-GEMM: act = silu(Hg@Ug) * (Hu@Uu) ----------------
__global__ __launch_bounds__(256) void k_swiglu(
    const float* __restrict__ uout_gate, const float* __restrict__ uout_up)
{
    int ti = blockIdx.x;
    if (ti >= g_ntiles) return;
    int g = g_tile_g[ti], row0 = g_tile_row[ti], rend = g_off[g+1];
    int n0 = blockIdx.y*BN;
    __shared__ float Ag[BK][BM+4], Au[BK][BM+4];
    __shared__ float Bg[BK][BN],   Bu[BK][BN];
    int tid = threadIdx.x, tx4 = (tid&15)*4, ty4 = (tid>>4)*4;
    const float* Agp = g_xg + row0*RR;
    const float* Aup = g_xu + row0*RR;
    const float* Bgp = uout_gate + g*RR*DFFN + n0;
    const float* Bup = uout_up   + g*RR*DFFN + n0;
    float accg[4][4] = {}, accu[4][4] = {};
    for (int k0 = 0; k0 < RR; k0 += BK) {
        load_tiles(Ag, Bg, Agp, RR, Bgp, DFFN, k0, tid);
        load_tiles(Au, Bu, Aup, RR, Bup, DFFN, k0, tid);
        __syncthreads();
        mma_step(Ag, Bg, accg, ty4, tx4);
        mma_step(Au, Bu, accu, ty4, tx4);
        __syncthreads();
    }
#pragma unroll
    for (int i = 0; i < 4; i++) {
        int p = row0 + ty4 + i;
        if (p < rend) {
            float4 v;
#pragma unroll
            for (int j = 0; j < 4; j++) {
                float gv = accg[i][j];
                ((float*)&v)[j] = (gv / (1.f + expf(-gv))) * accu[i][j];
            }
            *(float4*)(g_act + p*DFFN + n0 + tx4) = v;
        }
    }
}

// ---------------- K7: xd = act @ uin_down[g]  (K=1024, N=64) ----------------
__global__ __launch_bounds__(256) void k_down_in(const float* __restrict__ uin_down)
{
    int ti = blockIdx.x;
    if (ti >= g_ntiles) return;
    int g = g_tile_g[ti], row0 = g_tile_row[ti], rend = g_off[g+1];
    __shared__ float Asm[BK][BM+4], Bsm[BK][BN];
    int tid = threadIdx.x, tx4 = (tid&15)*4, ty4 = (tid>>4)*4;
    const float* A = g_act + row0*DFFN;
    const float* B = uin_down + g*DFFN*RR;
    float acc[4][4] = {};
    for (int k0 = 0; k0 < DFFN; k0 += BK) {
        load_tiles(Asm, Bsm, A, DFFN, B, RR, k0, tid);
        __syncthreads();
        mma_step(Asm, Bsm, acc, ty4, tx4);
        __syncthreads();
    }
#pragma unroll
    for (int i = 0; i < 4; i++) {
        int p = row0 + ty4 + i;
        if (p < rend)
            *(float4*)(g_xd + p*RR + tx4) = make_float4(acc[i][0], acc[i][1], acc[i][2], acc[i][3]);
    }
}

// ---------------- K8: Tucker core apply (down) ----------------
__global__ void k_core_down(const float* __restrict__ core_down)
{
    int p = blockIdx.x;
    int e = g_se[p];
    const float* core = core_down + e*RR*RR;
    __shared__ float xs[RR];
    int j = threadIdx.x;
    xs[j] = g_xd[p*RR + j];
    __syncthreads();
    float acc = 0.f;
#pragma unroll 8
    for (int r = 0; r < RR; r++) acc += xs[r] * core[r*RR + j];
    g_x2[p*RR + j] = acc;
}

// ---------------- K9: out_f[f] = w[f] * (x2 @ uout_down[g]) (written in ORIGINAL pair order) ----------------
__global__ __launch_bounds__(256) void k_out(const float* __restrict__ uout_down)
{
    int ti = blockIdx.x;
    if (ti >= g_ntiles) return;
    int g = g_tile_g[ti], row0 = g_tile_row[ti], rend = g_off[g+1];
    int n0 = blockIdx.y*BN;
    __shared__ float Asm[BK][BM+4], Bsm[BK][BN];
    int tid = threadIdx.x, tx4 = (tid&15)*4, ty4 = (tid>>4)*4;
    const float* A = g_x2 + row0*RR;
    const float* B = uout_down + g*RR*DD + n0;
    float acc[4][4] = {};
    for (int k0 = 0; k0 < RR; k0 += BK) {
        load_tiles(Asm, Bsm, A, RR, B, DD, k0, tid);
        __syncthreads();
        mma_step(Asm, Bsm, acc, ty4, tx4);
        __syncthreads();
    }
#pragma unroll
    for (int i = 0; i < 4; i++) {
        int p = row0 + ty4 + i;
        if (p < rend) {
            int f = g_sf[p];
            float w = g_sw[p];
            *(float4*)(g_outf + f*DD + n0 + tx4) =
                make_float4(acc[i][0]*w, acc[i][1]*w, acc[i][2]*w, acc[i][3]*w);
        }
    }
}

// ---------------- K10: deterministic segment-sum (K=8 contiguous rows per token) ----------------
__global__ void k_reduce(float* __restrict__ out)
{
    int d = blockIdx.x*blockDim.x + threadIdx.x;
    int t = blockIdx.y;
    float s = 0.f;
#pragma unroll
    for (int k = 0; k < KK; k++) s += g_outf[(t*KK + k)*DD + d];
    out[t*DD + d] = s;
}

// ---------------- launch ----------------
extern "C" void kernel_launch(void* const* d_in, const int* in_sizes, int n_in,
                              void* d_out, int out_size)
{
    const float* x         = (const float*)d_in[0];
    const float* Wg        = (const float*)d_in[1];
    const float* uin_gate  = (const float*)d_in[2];
    const float* core_gate = (const float*)d_in[3];
    const float* uout_gate = (const float*)d_in[4];
    const float* uin_up    = (const float*)d_in[5];
    const float* core_up   = (const float*)d_in[6];
    const float* uout_up   = (const float*)d_in[7];
    const float* uin_down  = (const float*)d_in[8];
    const float* core_down = (const float*)d_in[9];
    const float* uout_down = (const float*)d_in[10];
    float* out = (float*)d_out;

    k_logits   <<<dim3(TT/BM, NEXPN/BN), 256>>>(x, Wg);
    k_topk     <<<(TT*32 + 255)/256, 256>>>();
    k_sort     <<<1, 1024>>>();
    k_pre      <<<dim3(TT/BM, GG, 2), 256>>>(x, uin_gate, uin_up);
    k_core_gu  <<<dim3(FF, 2), RR>>>(core_gate, core_up);
    k_swiglu   <<<dim3(MAX_TILES, DFFN/BN), 256>>>(uout_gate, uout_up);
    k_down_in  <<<MAX_TILES, 256>>>(uin_down);
    k_core_down<<<FF, RR>>>(core_down);
    k_out      <<<dim3(MAX_TILES, DD/BN), 256>>>(uout_down);
    k_reduce   <<<dim3(DD/256, TT), 256>>>(out);
}